// round 2
// baseline (speedup 1.0000x reference)
#include <cuda_runtime.h>
#include <cuda_fp16.h>
#include <cstdint>

#define T_TOK 4096
#define H_DIM 1024
#define F_DIM 2816
#define N_EXP 8
#define TOTAL_ROWS (2*T_TOK)          // top-2 routing -> 8192 expert-rows
#define W_ELEMS (8ull*1024ull*2816ull)

// ---------------- scratch (__device__ globals; no runtime allocation) -------
__device__ __half g_wg16[W_ELEMS];
__device__ __half g_wu16[W_ELEMS];
__device__ __half g_wd16[W_ELEMS];
__device__ __half g_x16[(size_t)T_TOK * H_DIM];
__device__ __half g_gbuf[(size_t)TOTAL_ROWS * F_DIM];
__device__ __half g_ubuf[(size_t)TOTAL_ROWS * F_DIM];
__device__ __half g_hbuf[(size_t)TOTAL_ROWS * F_DIM];
__device__ int    g_counts[N_EXP];
__device__ int    g_cursor[N_EXP];
__device__ int    g_offs[N_EXP];
__device__ int    g_eid[TOTAL_ROWS];
__device__ float  g_ewt[TOTAL_ROWS];
__device__ int    g_rows[TOTAL_ROWS];   // position -> token
__device__ float  g_wv[TOTAL_ROWS];     // position -> combine weight
__device__ int    g_tile_e[80];
__device__ int    g_tile_r0[80];
__device__ int    g_tile_rows[80];
__device__ int    g_tile_count;

// ---------------- small helpers ---------------------------------------------
__device__ __forceinline__ unsigned smem_u32(const void* p) {
    return (unsigned)__cvta_generic_to_shared(p);
}
__device__ __forceinline__ void cp_async16(const void* smem, const void* g) {
    asm volatile("cp.async.cg.shared.global [%0], [%1], 16;"
                 :: "r"(smem_u32(smem)), "l"(g));
}
__device__ __forceinline__ void cp_commit() {
    asm volatile("cp.async.commit_group;" ::: "memory");
}
template <int N>
__device__ __forceinline__ void cp_wait() {
    asm volatile("cp.async.wait_group %0;" :: "n"(N) : "memory");
}
__device__ __forceinline__ void ldsm_x4(uint32_t r[4], const __half* p) {
    asm volatile("ldmatrix.sync.aligned.m8n8.x4.shared.b16 {%0,%1,%2,%3}, [%4];"
                 : "=r"(r[0]), "=r"(r[1]), "=r"(r[2]), "=r"(r[3])
                 : "r"(smem_u32(p)));
}
__device__ __forceinline__ void ldsm_x4_t(uint32_t r[4], const __half* p) {
    asm volatile("ldmatrix.sync.aligned.m8n8.x4.trans.shared.b16 {%0,%1,%2,%3}, [%4];"
                 : "=r"(r[0]), "=r"(r[1]), "=r"(r[2]), "=r"(r[3])
                 : "r"(smem_u32(p)));
}
__device__ __forceinline__ void mma_16816(float* c, const uint32_t* a,
                                          uint32_t b0, uint32_t b1) {
    asm volatile(
        "mma.sync.aligned.m16n8k16.row.col.f32.f16.f16.f32 "
        "{%0,%1,%2,%3},{%4,%5,%6,%7},{%8,%9},{%0,%1,%2,%3};"
        : "+f"(c[0]), "+f"(c[1]), "+f"(c[2]), "+f"(c[3])
        : "r"(a[0]), "r"(a[1]), "r"(a[2]), "r"(a[3]), "r"(b0), "r"(b1));
}

// ---------------- tiny kernels ----------------------------------------------
__global__ void init_kernel() {
    int i = threadIdx.x;
    if (i < N_EXP) { g_counts[i] = 0; g_cursor[i] = 0; }
}

__global__ void zero_out_kernel(float4* out) {
    size_t n = (size_t)T_TOK * H_DIM / 4;
    for (size_t i = blockIdx.x * (size_t)blockDim.x + threadIdx.x; i < n;
         i += (size_t)gridDim.x * blockDim.x)
        out[i] = make_float4(0.f, 0.f, 0.f, 0.f);
}

__global__ void convert_kernel(const float4* __restrict__ wg,
                               const float4* __restrict__ wu,
                               const float4* __restrict__ wd) {
    size_t n = W_ELEMS / 4;
    __half2* og = (__half2*)g_wg16;
    __half2* ou = (__half2*)g_wu16;
    __half2* od = (__half2*)g_wd16;
    for (size_t i = blockIdx.x * (size_t)blockDim.x + threadIdx.x; i < n;
         i += (size_t)gridDim.x * blockDim.x) {
        float4 a = wg[i];
        og[2*i]   = __floats2half2_rn(a.x, a.y);
        og[2*i+1] = __floats2half2_rn(a.z, a.w);
        float4 b = wu[i];
        ou[2*i]   = __floats2half2_rn(b.x, b.y);
        ou[2*i+1] = __floats2half2_rn(b.z, b.w);
        float4 c = wd[i];
        od[2*i]   = __floats2half2_rn(c.x, c.y);
        od[2*i+1] = __floats2half2_rn(c.z, c.w);
    }
}

// ---------------- RMSNorm + router + top2 ------------------------------------
__global__ void rmsnorm_router_kernel(const float* __restrict__ hs,
                                      const float* __restrict__ lnw,
                                      const float* __restrict__ rw) {
    const int t = blockIdx.x;
    const int tid = threadIdx.x, lane = tid & 31, warp = tid >> 5;

    float4 xv = *(const float4*)(hs + (size_t)t * H_DIM + tid * 4);
    float ss = xv.x*xv.x + xv.y*xv.y + xv.z*xv.z + xv.w*xv.w;
    #pragma unroll
    for (int o = 16; o; o >>= 1) ss += __shfl_xor_sync(0xffffffffu, ss, o);

    __shared__ float sred[8];
    __shared__ float sinv;
    if (lane == 0) sred[warp] = ss;
    __syncthreads();
    if (tid == 0) {
        float v = 0.f;
        #pragma unroll
        for (int w = 0; w < 8; w++) v += sred[w];
        sinv = rsqrtf(v * (1.0f / H_DIM) + 1e-5f);
    }
    __syncthreads();
    float inv = sinv;

    float4 lw = *(const float4*)(lnw + tid * 4);
    float xn[4] = {xv.x*inv*lw.x, xv.y*inv*lw.y, xv.z*inv*lw.z, xv.w*inv*lw.w};

    __half2* xd = (__half2*)(g_x16 + (size_t)t * H_DIM + tid * 4);
    xd[0] = __floats2half2_rn(xn[0], xn[1]);
    xd[1] = __floats2half2_rn(xn[2], xn[3]);

    float lp[8] = {0,0,0,0,0,0,0,0};
    #pragma unroll
    for (int r = 0; r < 4; r++) {
        const float4 w0 = *(const float4*)(rw + (size_t)(tid*4 + r) * N_EXP);
        const float4 w1 = *(const float4*)(rw + (size_t)(tid*4 + r) * N_EXP + 4);
        float xr = xn[r];
        lp[0] += xr*w0.x; lp[1] += xr*w0.y; lp[2] += xr*w0.z; lp[3] += xr*w0.w;
        lp[4] += xr*w1.x; lp[5] += xr*w1.y; lp[6] += xr*w1.z; lp[7] += xr*w1.w;
    }
    #pragma unroll
    for (int e = 0; e < 8; e++)
        #pragma unroll
        for (int o = 16; o; o >>= 1) lp[e] += __shfl_xor_sync(0xffffffffu, lp[e], o);

    __shared__ float sl[8][8];
    if (lane == 0) {
        #pragma unroll
        for (int e = 0; e < 8; e++) sl[warp][e] = lp[e];
    }
    __syncthreads();
    if (tid == 0) {
        float l[8], m = -1e30f;
        #pragma unroll
        for (int e = 0; e < 8; e++) {
            float v = 0.f;
            #pragma unroll
            for (int w = 0; w < 8; w++) v += sl[w][e];
            l[e] = v; m = fmaxf(m, v);
        }
        float p[8], s = 0.f;
        #pragma unroll
        for (int e = 0; e < 8; e++) { p[e] = expf(l[e] - m); s += p[e]; }
        float is = 1.f / s;
        int b1 = 0; float v1 = -1.f;
        #pragma unroll
        for (int e = 0; e < 8; e++) if (p[e] > v1) { v1 = p[e]; b1 = e; }
        int b2 = 0; float v2 = -1.f;
        #pragma unroll
        for (int e = 0; e < 8; e++) if (e != b1 && p[e] > v2) { v2 = p[e]; b2 = e; }
        g_eid[2*t]   = b1; g_ewt[2*t]   = v1 * is;
        g_eid[2*t+1] = b2; g_ewt[2*t+1] = v2 * is;
        atomicAdd(&g_counts[b1], 1);
        atomicAdd(&g_counts[b2], 1);
    }
}

__global__ void build_tiles_kernel() {
    int off = 0;
    for (int e = 0; e < N_EXP; e++) { g_offs[e] = off; off += g_counts[e]; }
    int tc = 0;
    for (int e = 0; e < N_EXP; e++) {
        int beg = g_offs[e], end = beg + g_counts[e];
        for (int r = beg; r < end; r += 128) {
            g_tile_e[tc] = e; g_tile_r0[tc] = r;
            g_tile_rows[tc] = min(128, end - r);
            tc++;
        }
    }
    g_tile_count = tc;
}

__global__ void scatter_kernel() {
    int i = blockIdx.x * blockDim.x + threadIdx.x;
    if (i < TOTAL_ROWS) {
        int e = g_eid[i];
        int pos = g_offs[e] + atomicAdd(&g_cursor[e], 1);
        g_rows[pos] = i >> 1;
        g_wv[pos] = g_ewt[i];
    }
}

// ---------------- grouped GEMM (mma.sync m16n8k16 fp16, f32 accum) ----------
// MODE 0: gate  (A = gathered x16, B = wg16, C = gbuf)
// MODE 1: up    (A = gathered x16, B = wu16, C = ubuf)
// MODE 2: down  (A = hbuf rows,    B = wd16, epilogue = weighted atomicAdd to out)
#define BM 128
#define BN 128
#define BKK 32
#define AST 40      // A smem row stride (halves): 32 + 8 pad
#define BST 136     // B smem row stride (halves): 128 + 8 pad

template <int MODE>
__global__ void __launch_bounds__(256, 2) gemm_kernel(float* __restrict__ out) {
    constexpr int KD  = (MODE == 2) ? F_DIM : H_DIM;
    constexpr int ND  = (MODE == 2) ? H_DIM : F_DIM;
    constexpr int LDA = (MODE == 2) ? F_DIM : H_DIM;
    constexpr bool GATHER = (MODE != 2);

    const __half* __restrict__ Ag = (MODE == 2) ? g_hbuf : g_x16;
    const __half* __restrict__ Bg =
        (MODE == 0) ? g_wg16 : (MODE == 1) ? g_wu16 : g_wd16;

    const int mt = blockIdx.y;
    if (mt >= g_tile_count) return;
    const int e    = g_tile_e[mt];
    const int r0   = g_tile_r0[mt];
    const int rows = g_tile_rows[mt];
    const int n0   = blockIdx.x * BN;

    __shared__ __half As[2][BM * AST];
    __shared__ __half Bs[2][BKK * BST];

    const int tid = threadIdx.x, lane = tid & 31, warp = tid >> 5;
    const int wm = warp >> 2, wn = warp & 3;

    // ---- per-thread load coordinates (fixed for whole K loop) ----
    const int rowA0 = tid >> 2, segA = (tid & 3) * 8;
    const int rowA1 = rowA0 + 64;
    int p0 = r0 + rowA0; if (p0 >= TOTAL_ROWS) p0 = TOTAL_ROWS - 1;
    int p1 = r0 + rowA1; if (p1 >= TOTAL_ROWS) p1 = TOTAL_ROWS - 1;
    const int ga0 = GATHER ? g_rows[p0] : p0;
    const int ga1 = GATHER ? g_rows[p1] : p1;
    const __half* aSrc0 = Ag + (size_t)ga0 * LDA + segA;
    const __half* aSrc1 = Ag + (size_t)ga1 * LDA + segA;

    const int rowB0 = tid >> 4, segB = (tid & 15) * 8;
    const int rowB1 = rowB0 + 16;
    const __half* bBase = Bg + (size_t)e * ((size_t)H_DIM * F_DIM) + n0;
    const __half* bSrc0 = bBase + (size_t)rowB0 * ND + segB;
    const __half* bSrc1 = bBase + (size_t)rowB1 * ND + segB;

    float acc[4][4][4];
    #pragma unroll
    for (int i = 0; i < 4; i++)
        #pragma unroll
        for (int j = 0; j < 4; j++)
            #pragma unroll
            for (int k = 0; k < 4; k++) acc[i][j][k] = 0.f;

    auto load_stage = [&](int buf, int k0) {
        cp_async16(&As[buf][rowA0 * AST + segA], aSrc0 + k0);
        cp_async16(&As[buf][rowA1 * AST + segA], aSrc1 + k0);
        cp_async16(&Bs[buf][rowB0 * BST + segB], bSrc0 + (size_t)k0 * ND);
        cp_async16(&Bs[buf][rowB1 * BST + segB], bSrc1 + (size_t)k0 * ND);
        cp_commit();
    };

    constexpr int KI = KD / BKK;
    load_stage(0, 0);
    int buf = 0;
    for (int it = 0; it < KI; ++it) {
        if (it + 1 < KI) { load_stage(buf ^ 1, (it + 1) * BKK); cp_wait<1>(); }
        else             { cp_wait<0>(); }
        __syncthreads();

        #pragma unroll
        for (int kk = 0; kk < BKK; kk += 16) {
            uint32_t ra[4][4];
            #pragma unroll
            for (int mi = 0; mi < 4; mi++) {
                const __half* pa = &As[buf][(wm*64 + mi*16 + (lane & 15)) * AST
                                            + kk + (lane >> 4) * 8];
                ldsm_x4(ra[mi], pa);
            }
            uint32_t rb[2][4];
            #pragma unroll
            for (int bj = 0; bj < 2; bj++) {
                int mat = lane >> 3, rr = lane & 7;
                const __half* pb = &Bs[buf][(kk + (mat & 1) * 8 + rr) * BST
                                            + wn*32 + bj*16 + (mat >> 1) * 8];
                ldsm_x4_t(rb[bj], pb);
            }
            #pragma unroll
            for (int mi = 0; mi < 4; mi++)
                #pragma unroll
                for (int nj = 0; nj < 4; nj++)
                    mma_16816(acc[mi][nj], ra[mi],
                              rb[nj >> 1][(nj & 1) * 2],
                              rb[nj >> 1][(nj & 1) * 2 + 1]);
        }
        __syncthreads();
        buf ^= 1;
    }

    // ---- epilogue ----
    #pragma unroll
    for (int mi = 0; mi < 4; mi++) {
        #pragma unroll
        for (int nj = 0; nj < 4; nj++) {
            int rr = wm*64 + mi*16 + (lane >> 2);
            int cc = n0 + wn*32 + nj*8 + (lane & 3) * 2;
            float* a = acc[mi][nj];
            if (MODE < 2) {
                __half* C = (MODE == 0) ? g_gbuf : g_ubuf;
                if (rr < rows)
                    *(__half2*)&C[(size_t)(r0 + rr) * F_DIM + cc] =
                        __floats2half2_rn(a[0], a[1]);
                if (rr + 8 < rows)
                    *(__half2*)&C[(size_t)(r0 + rr + 8) * F_DIM + cc] =
                        __floats2half2_rn(a[2], a[3]);
            } else {
                if (rr < rows) {
                    int tok = g_rows[r0 + rr]; float w = g_wv[r0 + rr];
                    atomicAdd(&out[(size_t)tok * H_DIM + cc],     w * a[0]);
                    atomicAdd(&out[(size_t)tok * H_DIM + cc + 1], w * a[1]);
                }
                if (rr + 8 < rows) {
                    int tok = g_rows[r0 + rr + 8]; float w = g_wv[r0 + rr + 8];
                    atomicAdd(&out[(size_t)tok * H_DIM + cc],     w * a[2]);
                    atomicAdd(&out[(size_t)tok * H_DIM + cc + 1], w * a[3]);
                }
            }
        }
    }
}

// ---------------- SwiGLU elementwise -----------------------------------------
__global__ void swiglu_kernel() {
    size_t n2 = (size_t)TOTAL_ROWS * F_DIM / 2;
    const __half2* g2p = (const __half2*)g_gbuf;
    const __half2* u2p = (const __half2*)g_ubuf;
    __half2* h2p = (__half2*)g_hbuf;
    for (size_t i = blockIdx.x * (size_t)blockDim.x + threadIdx.x; i < n2;
         i += (size_t)gridDim.x * blockDim.x) {
        float2 g = __half22float2(g2p[i]);
        float2 u = __half22float2(u2p[i]);
        float hx = g.x / (1.f + expf(-g.x)) * u.x;
        float hy = g.y / (1.f + expf(-g.y)) * u.y;
        h2p[i] = __floats2half2_rn(hx, hy);
    }
}

// ---------------- launch ------------------------------------------------------
extern "C" void kernel_launch(void* const* d_in, const int* in_sizes, int n_in,
                              void* d_out, int out_size) {
    const float* hs  = (const float*)d_in[0];
    const float* lnw = (const float*)d_in[1];
    const float* rw  = (const float*)d_in[2];
    const float* wg  = (const float*)d_in[3];
    const float* wu  = (const float*)d_in[4];
    const float* wd  = (const float*)d_in[5];
    float* out = (float*)d_out;

    init_kernel<<<1, 32>>>();
    convert_kernel<<<1184, 256>>>((const float4*)wg, (const float4*)wu,
                                  (const float4*)wd);
    rmsnorm_router_kernel<<<T_TOK, 256>>>(hs, lnw, rw);
    build_tiles_kernel<<<1, 1>>>();
    scatter_kernel<<<32, 256>>>();
    zero_out_kernel<<<512, 256>>>((float4*)d_out);

    gemm_kernel<0><<<dim3(F_DIM / BN, 72), 256>>>(out);   // gate
    gemm_kernel<1><<<dim3(F_DIM / BN, 72), 256>>>(out);   // up
    swiglu_kernel<<<1184, 256>>>();
    gemm_kernel<2><<<dim3(H_DIM / BN, 72), 256>>>(out);   // down + scatter-add
}